// round 1
// baseline (speedup 1.0000x reference)
#include <cuda_runtime.h>
#include <math.h>

// ---------------- problem constants ----------------
#define BGR   10000          // graphs
#define NN    5              // nodes/graph
#define NFR   8              // frames
#define NH    (BGR*NN)       // 50000
#define RTOT  (NFR*NH)       // 400000 expanded rows
#define HID   96
#define EPG   20             // edges per graph
#define ETOT  (BGR*EPG)      // 200000
#define NL    4

// ---------------- device scratch ----------------
__device__ float g_X [RTOT*HID];
__device__ float g_T [RTOT*HID];
__device__ float g_A [RTOT*HID];
__device__ float g_PR[RTOT*HID];
__device__ float g_PC[RTOT*HID];
__device__ float g_C [ETOT*HID];
__device__ float g_V [BGR*9];
__device__ float g_cen[BGR*3];

__device__ __forceinline__ float sgn(int o, int j) {
    return ((o >> (2 - j)) & 1) ? -1.f : 1.f;
}
__device__ __forceinline__ float silu(float v) {
    return v * (1.f / (1.f + __expf(-v)));
}

// ---------------- 3x3 symmetric eigh (double, ascending columns) ----------------
__device__ inline void cross3d(const double* a, const double* b, double* c) {
    c[0] = a[1]*b[2] - a[2]*b[1];
    c[1] = a[2]*b[0] - a[0]*b[2];
    c[2] = a[0]*b[1] - a[1]*b[0];
}
__device__ inline void eigvec3(double a00,double a01,double a02,double a11,double a12,double a22,
                               double lam, double* v) {
    double r0[3] = {a00-lam, a01, a02};
    double r1[3] = {a01, a11-lam, a12};
    double r2[3] = {a02, a12, a22-lam};
    double c0[3], c1[3], c2[3];
    cross3d(r0, r1, c0); cross3d(r0, r2, c1); cross3d(r1, r2, c2);
    double n0 = c0[0]*c0[0]+c0[1]*c0[1]+c0[2]*c0[2];
    double n1 = c1[0]*c1[0]+c1[1]*c1[1]+c1[2]*c1[2];
    double n2 = c2[0]*c2[0]+c2[1]*c2[1]+c2[2]*c2[2];
    double* best = c0; double nb = n0;
    if (n1 > nb) { best = c1; nb = n1; }
    if (n2 > nb) { best = c2; nb = n2; }
    if (nb < 1e-300) { v[0]=1.0; v[1]=0.0; v[2]=0.0; return; }
    double inv = 1.0 / sqrt(nb);
    v[0] = best[0]*inv; v[1] = best[1]*inv; v[2] = best[2]*inv;
}
// V row-major V[i*3+j]: column j = eigenvector of j-th smallest eigenvalue
__device__ inline void eigh3(double a00,double a01,double a02,double a11,double a12,double a22,
                             float* V) {
    double p1 = a01*a01 + a02*a02 + a12*a12;
    double q  = (a00 + a11 + a22) / 3.0;
    double b00 = a00-q, b11 = a11-q, b22 = a22-q;
    double p2 = b00*b00 + b11*b11 + b22*b22 + 2.0*p1;
    if (p2 < 1e-60) {  // (near) multiple of identity
        V[0]=1.f;V[1]=0.f;V[2]=0.f; V[3]=0.f;V[4]=1.f;V[5]=0.f; V[6]=0.f;V[7]=0.f;V[8]=1.f;
        return;
    }
    double p = sqrt(p2 / 6.0);
    double inv = 1.0 / p;
    double c00=b00*inv, c01=a01*inv, c02=a02*inv, c11=b11*inv, c12=a12*inv, c22=b22*inv;
    double det = c00*(c11*c22 - c12*c12) - c01*(c01*c22 - c12*c02) + c02*(c01*c12 - c11*c02);
    double r = 0.5 * det;
    r = fmin(1.0, fmax(-1.0, r));
    double phi  = acos(r) / 3.0;
    double lmax = q + 2.0*p*cos(phi);
    double lmin = q + 2.0*p*cos(phi + 2.0943951023931953);
    double vmin[3], vmax[3], vmid[3];
    eigvec3(a00,a01,a02,a11,a12,a22, lmin, vmin);
    eigvec3(a00,a01,a02,a11,a12,a22, lmax, vmax);
    cross3d(vmax, vmin, vmid);
    double nm = sqrt(vmid[0]*vmid[0]+vmid[1]*vmid[1]+vmid[2]*vmid[2]);
    double invm = (nm > 1e-300) ? 1.0/nm : 0.0;
    vmid[0]*=invm; vmid[1]*=invm; vmid[2]*=invm;
    V[0]=(float)vmin[0]; V[3]=(float)vmin[1]; V[6]=(float)vmin[2];
    V[1]=(float)vmid[0]; V[4]=(float)vmid[1]; V[7]=(float)vmid[2];
    V[2]=(float)vmax[0]; V[5]=(float)vmax[1]; V[8]=(float)vmax[2];
}

// ---------------- kernel: initial frames (1 thread / graph) ----------------
__global__ void frame_kernel(const float* __restrict__ h) {
    int b = blockIdx.x * blockDim.x + threadIdx.x;
    if (b >= BGR) return;
    const float* hp = h + (size_t)(b*NN)*6;
    double P[NN][3];
    double c0=0, c1=0, c2=0;
    for (int p = 0; p < NN; p++) {
        P[p][0] = hp[p*6+0]; P[p][1] = hp[p*6+1]; P[p][2] = hp[p*6+2];
        c0 += P[p][0]; c1 += P[p][1]; c2 += P[p][2];
    }
    c0 *= 0.2; c1 *= 0.2; c2 *= 0.2;
    double a00=0,a01=0,a02=0,a11=0,a12=0,a22=0;
    for (int p = 0; p < NN; p++) {
        double d0 = P[p][0]-c0, d1 = P[p][1]-c1, d2 = P[p][2]-c2;
        a00 += d0*d0; a01 += d0*d1; a02 += d0*d2;
        a11 += d1*d1; a12 += d1*d2; a22 += d2*d2;
    }
    float V[9];
    eigh3(a00,a01,a02,a11,a12,a22, V);
    for (int i = 0; i < 9; i++) g_V[b*9+i] = V[i];
    g_cen[b*3+0] = (float)c0; g_cen[b*3+1] = (float)c1; g_cen[b*3+2] = (float)c2;
}

// ---------------- kernel: frame transform + embedding (block = graph-frame) ----------------
__global__ __launch_bounds__(96) void embed_kernel(const float* __restrict__ h,
                                                   const float* __restrict__ Wg,
                                                   const float* __restrict__ bg) {
    int u = blockIdx.x;             // 0..79999
    int g = u >> 3, o = u & 7;
    __shared__ float in6[NN][6];
    __shared__ float Vs[9];
    __shared__ float cen[3];
    int tid = threadIdx.x;
    if (tid < 9)  Vs[tid] = g_V[g*9+tid];
    if (tid >= 9 && tid < 12) cen[tid-9] = g_cen[g*3 + tid - 9];
    __syncthreads();
    if (tid < 30) {
        int p = tid / 6, k = tid - p*6;
        int i = k % 3; bool vel = (k >= 3);
        const float* hp = &h[(size_t)(g*NN + p)*6];
        float x0, x1, x2;
        if (vel) { x0 = hp[3]; x1 = hp[4]; x2 = hp[5]; }
        else     { x0 = hp[0]-cen[0]; x1 = hp[1]-cen[1]; x2 = hp[2]-cen[2]; }
        float val = Vs[0*3+i]*x0 + Vs[1*3+i]*x1 + Vs[2*3+i]*x2;  // (V^T x)_i
        in6[p][k] = sgn(o, i) * val;
    }
    __syncthreads();
    int j = tid;
    float bv = bg[j];
    for (int p = 0; p < NN; p++) {
        float s = bv;
        #pragma unroll
        for (int k = 0; k < 6; k++) s += in6[p][k] * Wg[k*96 + j];
        g_X[(size_t)(o*NH + g*NN + p)*HID + j] = s;
    }
}

// ---------------- generic dense: OUT = (cat[INa,INb] @ W + bias), optional silu ----------------
// rows = RTOT fixed, 64-row tiles, 192 threads, thread tile 8 rows x 4 cols
#define DENSE_SMEM ((96*96 + 64*97)*4)
__global__ __launch_bounds__(192) void dense_k(const float* __restrict__ INa,
                                               const float* __restrict__ INb,
                                               const float* __restrict__ W,
                                               const float* __restrict__ bias,
                                               float* __restrict__ OUT,
                                               int nhalves, int dosilu) {
    extern __shared__ float sm[];
    float* Ws = sm;             // [96][96]
    float* At = sm + 96*96;     // [64][97]
    int tid = threadIdx.x;
    int tx = tid % 24, ty = tid / 24;
    int row0 = blockIdx.x * 64;
    float acc[8][4];
    #pragma unroll
    for (int e = 0; e < 8; e++) { acc[e][0]=0.f; acc[e][1]=0.f; acc[e][2]=0.f; acc[e][3]=0.f; }
    for (int hh = 0; hh < nhalves; hh++) {
        const float* IN = hh ? INb : INa;
        const float* Wh = W + hh*96*96;
        for (int idx = tid; idx < 96*96; idx += 192) Ws[idx] = Wh[idx];
        for (int idx = tid; idx < 64*96; idx += 192) {
            int r = idx / 96, k = idx - r*96;
            At[r*97 + k] = IN[(size_t)(row0 + r)*96 + k];
        }
        __syncthreads();
        #pragma unroll 4
        for (int k = 0; k < 96; k++) {
            float4 w4 = *(const float4*)&Ws[k*96 + tx*4];
            #pragma unroll
            for (int e = 0; e < 8; e++) {
                float a = At[(ty*8 + e)*97 + k];
                acc[e][0] += a*w4.x; acc[e][1] += a*w4.y;
                acc[e][2] += a*w4.z; acc[e][3] += a*w4.w;
            }
        }
        __syncthreads();
    }
    float b0=0.f, b1=0.f, b2=0.f, b3=0.f;
    if (bias) { b0 = bias[tx*4+0]; b1 = bias[tx*4+1]; b2 = bias[tx*4+2]; b3 = bias[tx*4+3]; }
    #pragma unroll
    for (int e = 0; e < 8; e++) {
        int r = row0 + ty*8 + e;
        float v0 = acc[e][0]+b0, v1 = acc[e][1]+b1, v2 = acc[e][2]+b2, v3 = acc[e][3]+b3;
        if (dosilu) { v0 = silu(v0); v1 = silu(v1); v2 = silu(v2); v3 = silu(v3); }
        float4 ov = make_float4(v0, v1, v2, v3);
        *(float4*)&OUT[(size_t)r*96 + tx*4] = ov;
    }
}

// ---------------- edge-attr part of edge MLP1 (bias folded in), per base edge ----------------
__global__ void eattr_kernel(const float* __restrict__ ea,
                             const float* __restrict__ We,
                             const float* __restrict__ eb1g) {
    int idx = blockIdx.x * blockDim.x + threadIdx.x;
    if (idx >= ETOT*96) return;
    int e = idx / 96, j = idx - e*96;
    float a0 = __ldg(&ea[e*2+0]), a1 = __ldg(&ea[e*2+1]);
    g_C[idx] = a0*We[j] + a1*We[96+j] + eb1g[j];
}

// ---------------- edge kernel: m1=silu(PR[r]+PC[c]+C), m2=silu(m1@W2+b2), agg by source ----------------
__global__ __launch_bounds__(120) void edge_kernel(const float* __restrict__ W2g,
                                                   const float* __restrict__ eb2g) {
    __shared__ float W2[96*96];
    __shared__ float m1[20*97];
    __shared__ float eb2s[96];
    int tid = threadIdx.x;
    for (int idx = tid; idx < 96*96; idx += 120) W2[idx] = W2g[idx];
    if (tid < 96) eb2s[tid] = eb2g[tid];
    __syncthreads();
    int tx = tid % 24, ty = tid / 24;   // ty in [0,5): source node; tx: col quad
    for (int it = 0; it < 8; it++) {
        int u = blockIdx.x*8 + it;      // graph-frame unit
        int g = u >> 3, o = u & 7;
        int nb = o*NH + g*NN;
        int eb = g*EPG;
        for (int idx = tid; idx < 20*96; idx += 120) {
            int le = idx / 96, j = idx - le*96;
            int r = le >> 2, cl = le & 3;
            int c = cl + (cl >= r ? 1 : 0);
            float v = g_PR[(size_t)(nb+r)*96 + j] + g_PC[(size_t)(nb+c)*96 + j]
                    + g_C[(size_t)(eb+le)*96 + j];
            m1[le*97 + j] = silu(v);
        }
        __syncthreads();
        float acc[4][4];
        #pragma unroll
        for (int e = 0; e < 4; e++) { acc[e][0]=0.f; acc[e][1]=0.f; acc[e][2]=0.f; acc[e][3]=0.f; }
        #pragma unroll 4
        for (int k = 0; k < 96; k++) {
            float4 w4 = *(const float4*)&W2[k*96 + tx*4];
            #pragma unroll
            for (int e = 0; e < 4; e++) {
                float a = m1[(ty*4 + e)*97 + k];
                acc[e][0] += a*w4.x; acc[e][1] += a*w4.y;
                acc[e][2] += a*w4.z; acc[e][3] += a*w4.w;
            }
        }
        float4 bb = *(const float4*)&eb2s[tx*4];
        float s0=0.f, s1=0.f, s2=0.f, s3=0.f;
        #pragma unroll
        for (int e = 0; e < 4; e++) {
            s0 += silu(acc[e][0] + bb.x);
            s1 += silu(acc[e][1] + bb.y);
            s2 += silu(acc[e][2] + bb.z);
            s3 += silu(acc[e][3] + bb.w);
        }
        float4 ov = make_float4(s0, s1, s2, s3);
        *(float4*)&g_A[(size_t)(nb + ty)*96 + tx*4] = ov;
        __syncthreads();
    }
}

// ---------------- relatent: invert_latent + create_latent fused (block = graph, 160 thr) ----------------
__global__ __launch_bounds__(160) void relatent_kernel() {
    int b = blockIdx.x;
    int tid = threadIdx.x;
    int lane = tid & 31, warp = tid >> 5;   // warp == node p, lane == f
    int p = warp, f = lane;
    __shared__ float Vs[9];
    __shared__ float Vn[9];
    __shared__ float scen[3];
    __shared__ float wred[5][6];
    if (tid < 9) Vs[tid] = g_V[b*9 + tid];
    __syncthreads();
    float pm0 = 0.f, pm1 = 0.f, pm2 = 0.f;
    #pragma unroll
    for (int o = 0; o < NFR; o++) {
        const float* xr = &g_X[(size_t)(o*NH + b*NN + p)*HID + 3*f];
        float x0 = xr[0], x1 = xr[1], x2 = xr[2];
        float s0 = sgn(o,0), s1 = sgn(o,1), s2 = sgn(o,2);
        float y0 = s0*x0, y1 = s1*x1, y2 = s2*x2;
        pm0 += Vs[0]*y0 + Vs[1]*y1 + Vs[2]*y2;   // (F x)_i = sum_j V[i][j] s_j x_j
        pm1 += Vs[3]*y0 + Vs[4]*y1 + Vs[5]*y2;
        pm2 += Vs[6]*y0 + Vs[7]*y1 + Vs[8]*y2;
    }
    pm0 *= 0.125f; pm1 *= 0.125f; pm2 *= 0.125f;
    // center reduce
    float r0 = pm0, r1 = pm1, r2 = pm2;
    for (int off = 16; off; off >>= 1) {
        r0 += __shfl_down_sync(0xffffffffu, r0, off);
        r1 += __shfl_down_sync(0xffffffffu, r1, off);
        r2 += __shfl_down_sync(0xffffffffu, r2, off);
    }
    if (lane == 0) { wred[warp][0]=r0; wred[warp][1]=r1; wred[warp][2]=r2; }
    __syncthreads();
    if (tid == 0) {
        float c0=0,c1=0,c2=0;
        for (int w = 0; w < 5; w++) { c0+=wred[w][0]; c1+=wred[w][1]; c2+=wred[w][2]; }
        scen[0] = c0/160.f; scen[1] = c1/160.f; scen[2] = c2/160.f;
    }
    __syncthreads();
    float d0 = pm0 - scen[0], d1 = pm1 - scen[1], d2 = pm2 - scen[2];
    float q[6] = { d0*d0, d0*d1, d0*d2, d1*d1, d1*d2, d2*d2 };
    #pragma unroll
    for (int i = 0; i < 6; i++) {
        float v = q[i];
        for (int off = 16; off; off >>= 1) v += __shfl_down_sync(0xffffffffu, v, off);
        q[i] = v;
    }
    if (lane == 0) { for (int i = 0; i < 6; i++) wred[warp][i] = q[i]; }
    __syncthreads();
    if (tid == 0) {
        double A[6] = {0,0,0,0,0,0};
        for (int w = 0; w < 5; w++)
            for (int i = 0; i < 6; i++) A[i] += (double)wred[w][i];
        float V[9];
        eigh3(A[0],A[1],A[2],A[3],A[4],A[5], V);
        for (int i = 0; i < 9; i++) { Vn[i] = V[i]; g_V[b*9+i] = V[i]; }
    }
    __syncthreads();
    // new frame coords: y_i = sum_j Vn[j][i] * d_j ; write 8 sign-flipped frames
    float y0 = Vn[0]*d0 + Vn[3]*d1 + Vn[6]*d2;
    float y1 = Vn[1]*d0 + Vn[4]*d1 + Vn[7]*d2;
    float y2 = Vn[2]*d0 + Vn[5]*d1 + Vn[8]*d2;
    #pragma unroll
    for (int o = 0; o < NFR; o++) {
        float* xr = &g_X[(size_t)(o*NH + b*NN + p)*HID + 3*f];
        xr[0] = sgn(o,0)*y0; xr[1] = sgn(o,1)*y1; xr[2] = sgn(o,2)*y2;
    }
}

// ---------------- final: decode (96->3) + invert_frame (block = node, 8 warps = 8 frames) ----------------
__global__ __launch_bounds__(256) void out_kernel(const float* __restrict__ dw2,
                                                  const float* __restrict__ db2,
                                                  float* __restrict__ out) {
    int node = blockIdx.x;          // 0..NH-1
    int b = node / NN;
    int tid = threadIdx.x, lane = tid & 31, o = tid >> 5;
    __shared__ float acc[8][3];
    __shared__ float Vl[9];
    __shared__ float cen3[3];
    if (tid < 9) Vl[tid] = g_V[b*9 + tid];
    if (tid >= 9 && tid < 12) cen3[tid-9] = g_cen[b*3 + tid - 9];
    __syncthreads();
    const float* Tr = &g_T[(size_t)(o*NH + node)*HID];
    float q0 = 0.f, q1 = 0.f, q2 = 0.f;
    for (int k = lane; k < 96; k += 32) {
        float t = Tr[k];
        q0 += t * dw2[k*3+0]; q1 += t * dw2[k*3+1]; q2 += t * dw2[k*3+2];
    }
    for (int off = 16; off; off >>= 1) {
        q0 += __shfl_down_sync(0xffffffffu, q0, off);
        q1 += __shfl_down_sync(0xffffffffu, q1, off);
        q2 += __shfl_down_sync(0xffffffffu, q2, off);
    }
    if (lane == 0) {
        q0 += db2[0]; q1 += db2[1]; q2 += db2[2];
        float s0 = sgn(o,0)*q0, s1 = sgn(o,1)*q1, s2 = sgn(o,2)*q2;
        acc[o][0] = Vl[0]*s0 + Vl[1]*s1 + Vl[2]*s2;
        acc[o][1] = Vl[3]*s0 + Vl[4]*s1 + Vl[5]*s2;
        acc[o][2] = Vl[6]*s0 + Vl[7]*s1 + Vl[8]*s2;
    }
    __syncthreads();
    if (tid < 3) {
        float s = 0.f;
        for (int oo = 0; oo < NFR; oo++) s += acc[oo][tid];
        out[(size_t)node*3 + tid] = s * 0.125f + cen3[tid];
    }
}

// ---------------- host launcher ----------------
extern "C" void kernel_launch(void* const* d_in, const int* in_sizes, int n_in,
                              void* d_out, int out_size) {
    const float* h     = (const float*)d_in[0];
    const float* ea    = (const float*)d_in[1];
    const float* emb_w = (const float*)d_in[2];
    const float* emb_b = (const float*)d_in[3];
    const float* ew1   = (const float*)d_in[4];   // [4,194,96]
    const float* eb1   = (const float*)d_in[5];   // [4,96]
    const float* ew2   = (const float*)d_in[6];   // [4,96,96]
    const float* eb2   = (const float*)d_in[7];   // [4,96]
    const float* nw1   = (const float*)d_in[8];   // [4,192,96]
    const float* nb1   = (const float*)d_in[9];
    const float* nw2   = (const float*)d_in[10];  // [4,96,96]
    const float* nb2   = (const float*)d_in[11];
    const float* dw1   = (const float*)d_in[12];  // [96,96]
    const float* db1   = (const float*)d_in[13];
    const float* dw2   = (const float*)d_in[14];  // [96,3]
    const float* db2   = (const float*)d_in[15];
    float* out = (float*)d_out;

    float *X, *T, *A, *PR, *PC;
    cudaGetSymbolAddress((void**)&X,  g_X);
    cudaGetSymbolAddress((void**)&T,  g_T);
    cudaGetSymbolAddress((void**)&A,  g_A);
    cudaGetSymbolAddress((void**)&PR, g_PR);
    cudaGetSymbolAddress((void**)&PC, g_PC);
    cudaFuncSetAttribute(dense_k, cudaFuncAttributeMaxDynamicSharedMemorySize, DENSE_SMEM);

    frame_kernel<<<(BGR + 127)/128, 128>>>(h);
    embed_kernel<<<BGR*NFR, 96>>>(h, emb_w, emb_b);

    const int DG = RTOT / 64;   // 6250 dense blocks
    for (int l = 0; l < NL; l++) {
        const float* ew1_l = ew1 + (size_t)l*194*96;
        // per-node halves of edge MLP1
        dense_k<<<DG, 192, DENSE_SMEM>>>(X, nullptr, ew1_l,          nullptr, PR, 1, 0);
        dense_k<<<DG, 192, DENSE_SMEM>>>(X, nullptr, ew1_l + 96*96,  nullptr, PC, 1, 0);
        // edge-attr half (+ eb1) over base edges
        eattr_kernel<<<(ETOT*96 + 255)/256, 256>>>(ea, ew1_l + 192*96, eb1 + l*96);
        // per-edge MLP2 + segment sum
        edge_kernel<<<BGR*NFR/8, 120>>>(ew2 + (size_t)l*96*96, eb2 + l*96);
        // node model
        dense_k<<<DG, 192, DENSE_SMEM>>>(X, A, nw1 + (size_t)l*192*96, nb1 + l*96, T, 2, 1);
        dense_k<<<DG, 192, DENSE_SMEM>>>(T, nullptr, nw2 + (size_t)l*96*96, nb2 + l*96, X, 1, 0);
        if (l < NL - 1) relatent_kernel<<<BGR, 160>>>();
    }
    // decoder
    dense_k<<<DG, 192, DENSE_SMEM>>>(X, nullptr, dw1, db1, T, 1, 1);
    out_kernel<<<NH, 256>>>(dw2, db2, out);
}